// round 16
// baseline (speedup 1.0000x reference)
#include <cuda_runtime.h>
#include <cuda_bf16.h>
#include <cstdint>

// ---------------------------------------------------------------------------
// TripletHardLoss: loss = mean(relu(max_{same}(dist) - min_{diff}(dist) + 0.3))
// dist[i][j] = sqrt(max(||xi||^2 + ||xj||^2 - 2 xi.xj, 0))
// R16: d^2-domain epilogue — sqrt is monotone, so masked max/min are taken
// over raw d^2 (no per-element sqrt/clamp); clamp at the 20 pre-atomic
// values, sqrt applied once per anchor in the last-block finale. Exact.
// Mainloop identical to R13-15: raw mma.sync + ldmatrix fine-grained
// pipeline, 3-stage cp.async, 128x128 triangle tiles, 2 CTAs/SM.
// ---------------------------------------------------------------------------

#define MAX_N 4096
#define MAX_D 2048

__device__ float           g_sq[MAX_N];
__device__ unsigned int    g_ap[MAX_N];   // max d2 (same label), float bits
__device__ unsigned int    g_an[MAX_N];   // min d2 (diff label), float bits
__device__ int             g_lbl[MAX_N];
__device__ unsigned int    g_done;        // zero-init; reset by last block
__device__ __nv_bfloat16   g_xb[(size_t)MAX_N * MAX_D];

// ---- tiling ----
#define BM 128
#define BN 128
#define KT 64                 // K per smem stage
#define LDA 72                // bf16 stage row stride (pad 8), 144B
#define NSTAGE 3
#define A_ELEMS (BM * LDA)                // 9216 bf16 per matrix
#define STAGE_ELEMS (2 * A_ELEMS)         // A+B per stage
#define STAGE_BYTES (STAGE_ELEMS * 2)     // 36864
#define OFF_META (NSTAGE * STAGE_BYTES)   // 110592
#define SMEM_BYTES (OFF_META + 4 * 128 * 4)

__device__ __forceinline__ uint32_t smem_u32(const void* p) {
    uint32_t a;
    asm("{ .reg .u64 t; cvta.to.shared.u64 t, %1; cvt.u32.u64 %0, t; }"
        : "=r"(a) : "l"(p));
    return a;
}
__device__ __forceinline__ void cp_async16(uint32_t dst, const void* src) {
    asm volatile("cp.async.cg.shared.global [%0], [%1], 16;"
                 :: "r"(dst), "l"(src) : "memory");
}
__device__ __forceinline__ void ldsm4(uint32_t addr, uint32_t* r) {
    asm volatile("ldmatrix.sync.aligned.m8n8.x4.shared.b16 {%0,%1,%2,%3}, [%4];"
                 : "=r"(r[0]), "=r"(r[1]), "=r"(r[2]), "=r"(r[3])
                 : "r"(addr));
}
__device__ __forceinline__ void mma16816(float* c, const uint32_t* a,
                                         uint32_t b0, uint32_t b1) {
    asm("mma.sync.aligned.m16n8k16.row.col.f32.bf16.bf16.f32 "
        "{%0,%1,%2,%3}, {%4,%5,%6,%7}, {%8,%9}, {%0,%1,%2,%3};"
        : "+f"(c[0]), "+f"(c[1]), "+f"(c[2]), "+f"(c[3])
        : "r"(a[0]), "r"(a[1]), "r"(a[2]), "r"(a[3]), "r"(b0), "r"(b1));
}

// ---- launch 0: fused prep: rowsq + bf16 convert + init + label narrow ----
__global__ void k_prep(const float* __restrict__ X,
                       const void* __restrict__ Y,
                       int n, int d) {
    int row = blockIdx.x;
    const int* Yi = (const int*)Y;
    int hv = 0;
    if (threadIdx.x < 64) hv = Yi[2 * threadIdx.x + 1];
    int any64 = __syncthreads_or(hv);

    const float4* xr = reinterpret_cast<const float4*>(X + (size_t)row * d);
    __nv_bfloat162* dst =
        reinterpret_cast<__nv_bfloat162*>(g_xb + (size_t)row * d);
    int nv = d >> 2;
    float s = 0.f;
    for (int i = threadIdx.x; i < nv; i += blockDim.x) {
        float4 v = xr[i];
        s += v.x * v.x + v.y * v.y + v.z * v.z + v.w * v.w;
        dst[i * 2 + 0] = __nv_bfloat162(__float2bfloat16(v.x),
                                        __float2bfloat16(v.y));
        dst[i * 2 + 1] = __nv_bfloat162(__float2bfloat16(v.z),
                                        __float2bfloat16(v.w));
    }
    __shared__ float sh[32];
    for (int o = 16; o > 0; o >>= 1) s += __shfl_xor_sync(0xffffffffu, s, o);
    if ((threadIdx.x & 31) == 0) sh[threadIdx.x >> 5] = s;
    __syncthreads();
    if (threadIdx.x < 32) {
        float v = (threadIdx.x < (blockDim.x >> 5)) ? sh[threadIdx.x] : 0.f;
        for (int o = 16; o > 0; o >>= 1) v += __shfl_xor_sync(0xffffffffu, v, o);
        if (threadIdx.x == 0) {
            g_sq[row]  = v;
            g_ap[row]  = 0u;
            g_an[row]  = 0x7F800000u;   // +inf
            g_lbl[row] = (any64 == 0)
                ? (int)reinterpret_cast<const long long*>(Y)[row]
                : Yi[row];
        }
    }
}

// ---- launch 1: raw-mma triangular Gram + d2-domain max/min + finale ----
__global__ __launch_bounds__(256, 2)
void k_mma(int n, int d, float* __restrict__ out) {
    extern __shared__ __align__(16) char smem[];
    const uint32_t sbase = smem_u32(smem);
    float* sqm = reinterpret_cast<float*>(smem + OFF_META);
    float* sqn = sqm + 128;
    int*   lbm = reinterpret_cast<int*>(sqn + 128);
    int*   lbn = lbm + 128;

    // triangular tile decode: block b -> (i >= j)
    int b = blockIdx.x;
    int i = (int)((sqrtf(8.0f * (float)b + 1.0f) - 1.0f) * 0.5f);
    while ((i + 1) * (i + 2) / 2 <= b) i++;
    while (i * (i + 1) / 2 > b) i--;
    int j = b - i * (i + 1) / 2;
    const int m0 = i * BM;
    const int n0 = j * BN;
    const bool diag = (m0 == n0);

    const int t    = threadIdx.x;
    const int wid  = t >> 5;
    const int lane = t & 31;
    const int wm   = wid & 3;     // 32-row slab
    const int wn   = wid >> 2;    // 64-col slab

    if (t < 128) {
        sqm[t] = g_sq[m0 + t];
        lbm[t] = g_lbl[m0 + t];
    } else {
        int c = t - 128;
        sqn[c] = g_sq[n0 + c];
        lbn[c] = g_lbl[n0 + c];
    }

    const __nv_bfloat16* Am = g_xb + (size_t)m0 * d;
    const __nv_bfloat16* Bn = g_xb + (size_t)n0 * d;

    // cp.async mapping: row=t>>1, cols (t&1)*32 + q*8, q=0..3 (full coverage)
    const int lrow = t >> 1;
    const int lc0  = (t & 1) * 32;

    auto issue_stage = [&](int it, int buf) {
        const int k0 = it * KT;
        uint32_t sa = sbase + buf * STAGE_BYTES;
        uint32_t sb = sa + A_ELEMS * 2;
#pragma unroll
        for (int q = 0; q < 4; q++) {
            int c8 = lc0 + q * 8;
            uint32_t so = (uint32_t)(lrow * LDA + c8) * 2;
            cp_async16(sa + so, Am + (size_t)lrow * d + k0 + c8);
            if (!diag)
                cp_async16(sb + so, Bn + (size_t)lrow * d + k0 + c8);
        }
        asm volatile("cp.async.commit_group;" ::: "memory");
    };

    // ldmatrix lane offsets (bytes within stage), canonical x4 layouts
    const int aRow = (lane & 7) + ((lane >> 3) & 1) * 8;
    const int aK   = (lane >> 4) * 8;
    const int bRow = (lane & 7) + (lane >> 4) * 8;
    const int bK   = ((lane >> 3) & 1) * 8;
    const uint32_t bBase = diag ? 0u : (uint32_t)(A_ELEMS * 2);
    uint32_t aOff[2], bOff[4];
#pragma unroll
    for (int mf = 0; mf < 2; mf++)
        aOff[mf] = (uint32_t)((wm * 32 + mf * 16 + aRow) * LDA + aK) * 2;
#pragma unroll
    for (int nq = 0; nq < 4; nq++)
        bOff[nq] = (uint32_t)((wn * 64 + nq * 16 + bRow) * LDA + bK) * 2
                   + bBase;

    float acc[2][8][4];
#pragma unroll
    for (int mf = 0; mf < 2; mf++)
#pragma unroll
        for (int nf = 0; nf < 8; nf++)
#pragma unroll
            for (int r = 0; r < 4; r++) acc[mf][nf][r] = 0.f;

    const int nIter = d / KT;
    issue_stage(0, 0);
    issue_stage(1, 1);

    int buf = 0;
    for (int it = 0; it < nIter; it++) {
        if (it + 1 < nIter)
            asm volatile("cp.async.wait_group 1;" ::: "memory");
        else
            asm volatile("cp.async.wait_group 0;" ::: "memory");
        __syncthreads();

        const uint32_t sg = sbase + buf * STAGE_BYTES;

        // preamble: A(slice0) + B(0,0), B(0,1)
        uint32_t a[2][2][4];     // [pipe][mf]
        uint32_t bbuf[3][4];     // rotating ring, depth 3
        ldsm4(sg + aOff[0], a[0][0]);
        ldsm4(sg + aOff[1], a[0][1]);
        ldsm4(sg + bOff[0], bbuf[0]);
        ldsm4(sg + bOff[1], bbuf[1]);

        if (it + 2 < nIter) {
            int nb = buf + 2;
            if (nb >= NSTAGE) nb -= NSTAGE;
            issue_stage(it + 2, nb);
        }

        // 16 steps: step k = (slice s = k>>2, nq = k&3); 4 MMAs per step.
#pragma unroll
        for (int k = 0; k < 16; k++) {
            const int s  = k >> 2;
            const int nq = k & 3;
            const int cb = k % 3;
            const int ap = s & 1;
            if (k < 14) {
                const int k2 = k + 2;
                ldsm4(sg + bOff[k2 & 3] + (uint32_t)(k2 >> 2) * 32,
                      bbuf[k2 % 3]);
            }
            if (s < 3) {
                if (nq == 0)
                    ldsm4(sg + aOff[0] + (uint32_t)(s + 1) * 32, a[ap ^ 1][0]);
                else if (nq == 2)
                    ldsm4(sg + aOff[1] + (uint32_t)(s + 1) * 32, a[ap ^ 1][1]);
            }
            mma16816(acc[0][nq * 2 + 0], a[ap][0], bbuf[cb][0], bbuf[cb][1]);
            mma16816(acc[0][nq * 2 + 1], a[ap][0], bbuf[cb][2], bbuf[cb][3]);
            mma16816(acc[1][nq * 2 + 0], a[ap][1], bbuf[cb][0], bbuf[cb][1]);
            mma16816(acc[1][nq * 2 + 1], a[ap][1], bbuf[cb][2], bbuf[cb][3]);
        }
        if (++buf == NSTAGE) buf = 0;
    }

    // ---- register-direct epilogue, d2 domain (sqrt deferred; exact) ----
    // acc[mf][nf][h*2+w] -> row = wm*32 + mf*16 + (lane>>2) + h*8
    //                       col = wn*64 + nf*8 + (lane&3)*2 + w
    const float INF = __int_as_float(0x7F800000);
    const float NEG = -INF;
    const int cr = lane >> 2;
    const int cc = (lane & 3) * 2;

    float sm_r[4]; int lm_r[4];
#pragma unroll
    for (int mf = 0; mf < 2; mf++)
#pragma unroll
        for (int h = 0; h < 2; h++) {
            int r = wm * 32 + mf * 16 + cr + h * 8;
            sm_r[mf * 2 + h] = sqm[r];
            lm_r[mf * 2 + h] = lbm[r];
        }

    float rmp[4], rmn[4], cmp[16], cmn[16];
#pragma unroll
    for (int q = 0; q < 4; q++) { rmp[q] = NEG; rmn[q] = INF; }
#pragma unroll
    for (int q = 0; q < 16; q++) { cmp[q] = NEG; cmn[q] = INF; }

#pragma unroll
    for (int nf = 0; nf < 8; nf++)
#pragma unroll
        for (int w = 0; w < 2; w++) {
            const int col = wn * 64 + nf * 8 + cc + w;
            const float sc = sqn[col];
            const int   lc = lbn[col];
            const int   ci = nf * 2 + w;
#pragma unroll
            for (int mf = 0; mf < 2; mf++)
#pragma unroll
                for (int h = 0; h < 2; h++) {
                    const int ri = mf * 2 + h;
                    float d2 = fmaf(-2.f, acc[mf][nf][h * 2 + w],
                                    sm_r[ri] + sc);
                    if (lm_r[ri] == lc) {
                        rmp[ri] = fmaxf(rmp[ri], d2);
                        cmp[ci] = fmaxf(cmp[ci], d2);
                    } else {
                        rmn[ri] = fminf(rmn[ri], d2);
                        cmn[ci] = fminf(cmn[ci], d2);
                    }
                }
        }

    // row reduction across the quad (lanes sharing lane>>2): xor 1, 2
#pragma unroll
    for (int ri = 0; ri < 4; ri++) {
#pragma unroll
        for (int o = 1; o <= 2; o <<= 1) {
            rmp[ri] = fmaxf(rmp[ri], __shfl_xor_sync(0xffffffffu, rmp[ri], o));
            rmn[ri] = fminf(rmn[ri], __shfl_xor_sync(0xffffffffu, rmn[ri], o));
        }
    }
    if ((lane & 3) == 0) {
#pragma unroll
        for (int ri = 0; ri < 4; ri++) {
            int row = m0 + wm * 32 + (ri >> 1) * 16 + cr + (ri & 1) * 8;
            // clamp to >= 0 so float-bits atomics stay order-correct (exact:
            // reference clamps d2 at 0 before sqrt)
            atomicMax(&g_ap[row], __float_as_uint(fmaxf(rmp[ri], 0.f)));
            atomicMin(&g_an[row], __float_as_uint(fmaxf(rmn[ri], 0.f)));
        }
    }

    // column reduction across quads (xor 4, 8, 16); skip for diagonal tiles
    if (!diag) {
#pragma unroll
        for (int ci = 0; ci < 16; ci++) {
#pragma unroll
            for (int o = 4; o <= 16; o <<= 1) {
                cmp[ci] = fmaxf(cmp[ci],
                                __shfl_xor_sync(0xffffffffu, cmp[ci], o));
                cmn[ci] = fminf(cmn[ci],
                                __shfl_xor_sync(0xffffffffu, cmn[ci], o));
            }
        }
        if (lane < 4) {
#pragma unroll
            for (int ci = 0; ci < 16; ci++) {
                int col = n0 + wn * 64 + (ci >> 1) * 8 + lane * 2 + (ci & 1);
                atomicMax(&g_ap[col], __float_as_uint(fmaxf(cmp[ci], 0.f)));
                atomicMin(&g_an[col], __float_as_uint(fmaxf(cmn[ci], 0.f)));
            }
        }
    }

    // last-block finale: sqrt + mean hinge -> out[0]
    __shared__ unsigned int s_last;
    __threadfence();
    __syncthreads();
    if (t == 0)
        s_last = (atomicAdd(&g_done, 1u) == (unsigned)(gridDim.x - 1)) ? 1u : 0u;
    __syncthreads();
    if (s_last) {
        __threadfence();
        float s = 0.f;
        for (int idx = t; idx < n; idx += 256) {
            float ap = sqrtf(__uint_as_float(g_ap[idx]));
            float an = sqrtf(__uint_as_float(g_an[idx]));
            s += fmaxf(ap - an + 0.3f, 0.f);
        }
        __shared__ float sh[8];
        for (int o = 16; o > 0; o >>= 1)
            s += __shfl_xor_sync(0xffffffffu, s, o);
        if ((t & 31) == 0) sh[t >> 5] = s;
        __syncthreads();
        if (t < 32) {
            float v = (t < 8) ? sh[t] : 0.f;
            for (int o = 4; o > 0; o >>= 1)
                v += __shfl_xor_sync(0xffffffffu, v, o);
            if (t == 0) {
                out[0] = v / (float)n;
                g_done = 0;   // reset for next graph replay
            }
        }
    }
}

extern "C" void kernel_launch(void* const* d_in, const int* in_sizes, int n_in,
                              void* d_out, int out_size) {
    const float* X = (const float*)d_in[0];
    const void*  Y = d_in[1];
    int n = in_sizes[1];                 // 4096
    int d = in_sizes[0] / n;             // 2048
    float* out = (float*)d_out;

    static int smem_set = 0;
    if (!smem_set) {
        cudaFuncSetAttribute(k_mma,
                             cudaFuncAttributeMaxDynamicSharedMemorySize,
                             SMEM_BYTES);
        smem_set = 1;
    }

    k_prep<<<n, 256>>>(X, Y, n, d);

    int nt = n / BM;
    int nblocks = nt * (nt + 1) / 2;     // 528
    k_mma<<<nblocks, 256, SMEM_BYTES>>>(n, d, out);
}

// round 17
// speedup vs baseline: 1.2367x; 1.2367x over previous
#include <cuda_runtime.h>
#include <cuda_bf16.h>
#include <cstdint>

// ---------------------------------------------------------------------------
// TripletHardLoss: loss = mean(relu(max_{same}(dist) - min_{diff}(dist) + 0.3))
// dist[i][j] = sqrt(max(||xi||^2 + ||xj||^2 - 2 xi.xj, 0))
// R17: mbarrier producer/consumer pipeline replaces the per-stage
// __syncthreads — full/empty mbarriers (count=256), data-landed signaled by
// cp.async.mbarrier.arrive.noinc, warps may skew a full stage instead of
// reconverging. Mainloop compute + d2-domain register epilogue from R16.
// 128x128 triangle tiles, 3 smem stages, 2 CTAs/SM.
// ---------------------------------------------------------------------------

#define MAX_N 4096
#define MAX_D 2048

__device__ float           g_sq[MAX_N];
__device__ unsigned int    g_ap[MAX_N];   // max d2 (same label), float bits
__device__ unsigned int    g_an[MAX_N];   // min d2 (diff label), float bits
__device__ int             g_lbl[MAX_N];
__device__ unsigned int    g_done;        // zero-init; reset by last block
__device__ __nv_bfloat16   g_xb[(size_t)MAX_N * MAX_D];

// ---- tiling ----
#define BM 128
#define BN 128
#define KT 64                 // K per smem stage
#define LDA 72                // bf16 stage row stride (pad 8), 144B
#define NSTAGE 3
#define A_ELEMS (BM * LDA)                // 9216 bf16 per matrix
#define STAGE_ELEMS (2 * A_ELEMS)         // A+B per stage
#define STAGE_BYTES (STAGE_ELEMS * 2)     // 36864
#define OFF_META (NSTAGE * STAGE_BYTES)   // 110592
#define OFF_MBAR (OFF_META + 4 * 128 * 4) // full[3] then empty[3], 8B each
#define SMEM_BYTES (OFF_MBAR + 64)

__device__ __forceinline__ uint32_t smem_u32(const void* p) {
    uint32_t a;
    asm("{ .reg .u64 t; cvta.to.shared.u64 t, %1; cvt.u32.u64 %0, t; }"
        : "=r"(a) : "l"(p));
    return a;
}
__device__ __forceinline__ void cp_async16(uint32_t dst, const void* src) {
    asm volatile("cp.async.cg.shared.global [%0], [%1], 16;"
                 :: "r"(dst), "l"(src) : "memory");
}
__device__ __forceinline__ void mbar_init(uint32_t mbar, uint32_t cnt) {
    asm volatile("mbarrier.init.shared.b64 [%0], %1;"
                 :: "r"(mbar), "r"(cnt) : "memory");
}
__device__ __forceinline__ void mbar_arrive(uint32_t mbar) {
    asm volatile("mbarrier.arrive.shared.b64 _, [%0];"
                 :: "r"(mbar) : "memory");
}
__device__ __forceinline__ void cp_async_mbar_arrive(uint32_t mbar) {
    asm volatile("cp.async.mbarrier.arrive.noinc.shared.b64 [%0];"
                 :: "r"(mbar) : "memory");
}
__device__ __forceinline__ void mbar_wait(uint32_t mbar, uint32_t parity) {
    asm volatile(
        "{\n\t.reg .pred P1;\n\t"
        "WL_%=:\n\t"
        "mbarrier.try_wait.parity.acquire.cta.shared::cta.b64 P1, [%0], %1, 0x989680;\n\t"
        "@P1 bra.uni WD_%=;\n\t"
        "bra.uni WL_%=;\n\t"
        "WD_%=:\n\t}"
        :: "r"(mbar), "r"(parity) : "memory");
}
__device__ __forceinline__ void ldsm4(uint32_t addr, uint32_t* r) {
    asm volatile("ldmatrix.sync.aligned.m8n8.x4.shared.b16 {%0,%1,%2,%3}, [%4];"
                 : "=r"(r[0]), "=r"(r[1]), "=r"(r[2]), "=r"(r[3])
                 : "r"(addr));
}
__device__ __forceinline__ void mma16816(float* c, const uint32_t* a,
                                         uint32_t b0, uint32_t b1) {
    asm("mma.sync.aligned.m16n8k16.row.col.f32.bf16.bf16.f32 "
        "{%0,%1,%2,%3}, {%4,%5,%6,%7}, {%8,%9}, {%0,%1,%2,%3};"
        : "+f"(c[0]), "+f"(c[1]), "+f"(c[2]), "+f"(c[3])
        : "r"(a[0]), "r"(a[1]), "r"(a[2]), "r"(a[3]), "r"(b0), "r"(b1));
}

// ---- launch 0: fused prep: rowsq + bf16 convert + init + label narrow ----
__global__ void k_prep(const float* __restrict__ X,
                       const void* __restrict__ Y,
                       int n, int d) {
    int row = blockIdx.x;
    const int* Yi = (const int*)Y;
    int hv = 0;
    if (threadIdx.x < 64) hv = Yi[2 * threadIdx.x + 1];
    int any64 = __syncthreads_or(hv);

    const float4* xr = reinterpret_cast<const float4*>(X + (size_t)row * d);
    __nv_bfloat162* dst =
        reinterpret_cast<__nv_bfloat162*>(g_xb + (size_t)row * d);
    int nv = d >> 2;
    float s = 0.f;
    for (int i = threadIdx.x; i < nv; i += blockDim.x) {
        float4 v = xr[i];
        s += v.x * v.x + v.y * v.y + v.z * v.z + v.w * v.w;
        dst[i * 2 + 0] = __nv_bfloat162(__float2bfloat16(v.x),
                                        __float2bfloat16(v.y));
        dst[i * 2 + 1] = __nv_bfloat162(__float2bfloat16(v.z),
                                        __float2bfloat16(v.w));
    }
    __shared__ float sh[32];
    for (int o = 16; o > 0; o >>= 1) s += __shfl_xor_sync(0xffffffffu, s, o);
    if ((threadIdx.x & 31) == 0) sh[threadIdx.x >> 5] = s;
    __syncthreads();
    if (threadIdx.x < 32) {
        float v = (threadIdx.x < (blockDim.x >> 5)) ? sh[threadIdx.x] : 0.f;
        for (int o = 16; o > 0; o >>= 1) v += __shfl_xor_sync(0xffffffffu, v, o);
        if (threadIdx.x == 0) {
            g_sq[row]  = v;
            g_ap[row]  = 0u;
            g_an[row]  = 0x7F800000u;   // +inf
            g_lbl[row] = (any64 == 0)
                ? (int)reinterpret_cast<const long long*>(Y)[row]
                : Yi[row];
        }
    }
}

// ---- launch 1: raw-mma triangular Gram, mbarrier pipeline + finale ----
__global__ __launch_bounds__(256, 2)
void k_mma(int n, int d, float* __restrict__ out) {
    extern __shared__ __align__(16) char smem[];
    const uint32_t sbase = smem_u32(smem);
    float* sqm = reinterpret_cast<float*>(smem + OFF_META);
    float* sqn = sqm + 128;
    int*   lbm = reinterpret_cast<int*>(sqn + 128);
    int*   lbn = lbm + 128;
    const uint32_t mbF = sbase + OFF_MBAR;        // full[s]  = mbF + s*8
    const uint32_t mbE = mbF + 24;                // empty[s] = mbE + s*8

    // triangular tile decode: block b -> (i >= j)
    int b = blockIdx.x;
    int i = (int)((sqrtf(8.0f * (float)b + 1.0f) - 1.0f) * 0.5f);
    while ((i + 1) * (i + 2) / 2 <= b) i++;
    while (i * (i + 1) / 2 > b) i--;
    int j = b - i * (i + 1) / 2;
    const int m0 = i * BM;
    const int n0 = j * BN;
    const bool diag = (m0 == n0);

    const int t    = threadIdx.x;
    const int wid  = t >> 5;
    const int lane = t & 31;
    const int wm   = wid & 3;     // 32-row slab
    const int wn   = wid >> 2;    // 64-col slab

    if (t < 128) {
        sqm[t] = g_sq[m0 + t];
        lbm[t] = g_lbl[m0 + t];
    } else {
        int c = t - 128;
        sqn[c] = g_sq[n0 + c];
        lbn[c] = g_lbl[n0 + c];
    }
    if (t == 0) {
#pragma unroll
        for (int s = 0; s < NSTAGE; s++) {
            mbar_init(mbF + s * 8, 256);
            mbar_init(mbE + s * 8, 256);
        }
    }
    __syncthreads();   // mbarrier init + meta visible to all

    const __nv_bfloat16* Am = g_xb + (size_t)m0 * d;
    const __nv_bfloat16* Bn = g_xb + (size_t)n0 * d;

    // cp.async mapping: row=t>>1, cols (t&1)*32 + q*8, q=0..3 (full coverage)
    const int lrow = t >> 1;
    const int lc0  = (t & 1) * 32;

    auto issue_stage = [&](int it, int buf) {
        const int k0 = it * KT;
        uint32_t sa = sbase + buf * STAGE_BYTES;
        uint32_t sb = sa + A_ELEMS * 2;
#pragma unroll
        for (int q = 0; q < 4; q++) {
            int c8 = lc0 + q * 8;
            uint32_t so = (uint32_t)(lrow * LDA + c8) * 2;
            cp_async16(sa + so, Am + (size_t)lrow * d + k0 + c8);
            if (!diag)
                cp_async16(sb + so, Bn + (size_t)lrow * d + k0 + c8);
        }
        // signal full[buf] when THIS thread's cp.asyncs have landed
        cp_async_mbar_arrive(mbF + (uint32_t)buf * 8);
    };

    // ldmatrix lane offsets (bytes within stage), canonical x4 layouts
    const int aRow = (lane & 7) + ((lane >> 3) & 1) * 8;
    const int aK   = (lane >> 4) * 8;
    const int bRow = (lane & 7) + (lane >> 4) * 8;
    const int bK   = ((lane >> 3) & 1) * 8;
    const uint32_t bBase = diag ? 0u : (uint32_t)(A_ELEMS * 2);
    uint32_t aOff[2], bOff[4];
#pragma unroll
    for (int mf = 0; mf < 2; mf++)
        aOff[mf] = (uint32_t)((wm * 32 + mf * 16 + aRow) * LDA + aK) * 2;
#pragma unroll
    for (int nq = 0; nq < 4; nq++)
        bOff[nq] = (uint32_t)((wn * 64 + nq * 16 + bRow) * LDA + bK) * 2
                   + bBase;

    float acc[2][8][4];
#pragma unroll
    for (int mf = 0; mf < 2; mf++)
#pragma unroll
        for (int nf = 0; nf < 8; nf++)
#pragma unroll
            for (int r = 0; r < 4; r++) acc[mf][nf][r] = 0.f;

    const int nIter = d / KT;
    issue_stage(0, 0);
    issue_stage(1, 1);

    int cs = 0, cph = 0;            // consumer buffer + phase parity
    for (int it = 0; it < nIter; it++) {
        mbar_wait(mbF + (uint32_t)cs * 8, (uint32_t)cph);

        const uint32_t sg = sbase + cs * STAGE_BYTES;

        // preamble: A(slice0) + B(0,0), B(0,1)
        uint32_t a[2][2][4];     // [pipe][mf]
        uint32_t bbuf[3][4];     // rotating ring, depth 3
        ldsm4(sg + aOff[0], a[0][0]);
        ldsm4(sg + aOff[1], a[0][1]);
        ldsm4(sg + bOff[0], bbuf[0]);
        ldsm4(sg + bOff[1], bbuf[1]);

        // 16 steps: step k = (slice s = k>>2, nq = k&3); 4 MMAs per step.
#pragma unroll
        for (int k = 0; k < 16; k++) {
            const int s  = k >> 2;
            const int nq = k & 3;
            const int cb = k % 3;
            const int ap = s & 1;
            if (k < 14) {
                const int k2 = k + 2;
                ldsm4(sg + bOff[k2 & 3] + (uint32_t)(k2 >> 2) * 32,
                      bbuf[k2 % 3]);
            }
            if (s < 3) {
                if (nq == 0)
                    ldsm4(sg + aOff[0] + (uint32_t)(s + 1) * 32, a[ap ^ 1][0]);
                else if (nq == 2)
                    ldsm4(sg + aOff[1] + (uint32_t)(s + 1) * 32, a[ap ^ 1][1]);
            }
            mma16816(acc[0][nq * 2 + 0], a[ap][0], bbuf[cb][0], bbuf[cb][1]);
            mma16816(acc[0][nq * 2 + 1], a[ap][0], bbuf[cb][2], bbuf[cb][3]);
            mma16816(acc[1][nq * 2 + 0], a[ap][1], bbuf[cb][0], bbuf[cb][1]);
            mma16816(acc[1][nq * 2 + 1], a[ap][1], bbuf[cb][2], bbuf[cb][3]);
        }

        // done reading buffer cs for this round
        mbar_arrive(mbE + (uint32_t)cs * 8);

        // produce stage it+2 (buffer (it+2)%3): wait until all threads have
        // finished reading stage it-1 from that buffer, then refill.
        if (it + 2 < nIter) {
            const int jj   = it + 2;
            const int pbuf = (cs + 2 >= NSTAGE) ? cs + 2 - NSTAGE : cs + 2;
            if (jj >= NSTAGE) {
                const uint32_t ppar = (uint32_t)(((jj / 3) - 1) & 1);
                mbar_wait(mbE + (uint32_t)pbuf * 8, ppar);
            }
            issue_stage(jj, pbuf);
        }

        if (++cs == NSTAGE) { cs = 0; cph ^= 1; }
    }

    // ---- register-direct epilogue, d2 domain (sqrt deferred; exact) ----
    // acc[mf][nf][h*2+w] -> row = wm*32 + mf*16 + (lane>>2) + h*8
    //                       col = wn*64 + nf*8 + (lane&3)*2 + w
    const float INF = __int_as_float(0x7F800000);
    const float NEG = -INF;
    const int cr = lane >> 2;
    const int cc = (lane & 3) * 2;

    float sm_r[4]; int lm_r[4];
#pragma unroll
    for (int mf = 0; mf < 2; mf++)
#pragma unroll
        for (int h = 0; h < 2; h++) {
            int r = wm * 32 + mf * 16 + cr + h * 8;
            sm_r[mf * 2 + h] = sqm[r];
            lm_r[mf * 2 + h] = lbm[r];
        }

    float rmp[4], rmn[4], cmp[16], cmn[16];
#pragma unroll
    for (int q = 0; q < 4; q++) { rmp[q] = NEG; rmn[q] = INF; }
#pragma unroll
    for (int q = 0; q < 16; q++) { cmp[q] = NEG; cmn[q] = INF; }

#pragma unroll
    for (int nf = 0; nf < 8; nf++)
#pragma unroll
        for (int w = 0; w < 2; w++) {
            const int col = wn * 64 + nf * 8 + cc + w;
            const float sc = sqn[col];
            const int   lc = lbn[col];
            const int   ci = nf * 2 + w;
#pragma unroll
            for (int mf = 0; mf < 2; mf++)
#pragma unroll
                for (int h = 0; h < 2; h++) {
                    const int ri = mf * 2 + h;
                    float d2 = fmaf(-2.f, acc[mf][nf][h * 2 + w],
                                    sm_r[ri] + sc);
                    if (lm_r[ri] == lc) {
                        rmp[ri] = fmaxf(rmp[ri], d2);
                        cmp[ci] = fmaxf(cmp[ci], d2);
                    } else {
                        rmn[ri] = fminf(rmn[ri], d2);
                        cmn[ci] = fminf(cmn[ci], d2);
                    }
                }
        }

    // row reduction across the quad (lanes sharing lane>>2): xor 1, 2
#pragma unroll
    for (int ri = 0; ri < 4; ri++) {
#pragma unroll
        for (int o = 1; o <= 2; o <<= 1) {
            rmp[ri] = fmaxf(rmp[ri], __shfl_xor_sync(0xffffffffu, rmp[ri], o));
            rmn[ri] = fminf(rmn[ri], __shfl_xor_sync(0xffffffffu, rmn[ri], o));
        }
    }
    if ((lane & 3) == 0) {
#pragma unroll
        for (int ri = 0; ri < 4; ri++) {
            int row = m0 + wm * 32 + (ri >> 1) * 16 + cr + (ri & 1) * 8;
            // clamp to >= 0: float-bits atomic ordering + matches reference
            atomicMax(&g_ap[row], __float_as_uint(fmaxf(rmp[ri], 0.f)));
            atomicMin(&g_an[row], __float_as_uint(fmaxf(rmn[ri], 0.f)));
        }
    }

    // column reduction across quads (xor 4, 8, 16); skip for diagonal tiles
    if (!diag) {
#pragma unroll
        for (int ci = 0; ci < 16; ci++) {
#pragma unroll
            for (int o = 4; o <= 16; o <<= 1) {
                cmp[ci] = fmaxf(cmp[ci],
                                __shfl_xor_sync(0xffffffffu, cmp[ci], o));
                cmn[ci] = fminf(cmn[ci],
                                __shfl_xor_sync(0xffffffffu, cmn[ci], o));
            }
        }
        if (lane < 4) {
#pragma unroll
            for (int ci = 0; ci < 16; ci++) {
                int col = n0 + wn * 64 + (ci >> 1) * 8 + lane * 2 + (ci & 1);
                atomicMax(&g_ap[col], __float_as_uint(fmaxf(cmp[ci], 0.f)));
                atomicMin(&g_an[col], __float_as_uint(fmaxf(cmn[ci], 0.f)));
            }
        }
    }

    // last-block finale: sqrt + mean hinge -> out[0]
    __shared__ unsigned int s_last;
    __threadfence();
    __syncthreads();
    if (t == 0)
        s_last = (atomicAdd(&g_done, 1u) == (unsigned)(gridDim.x - 1)) ? 1u : 0u;
    __syncthreads();
    if (s_last) {
        __threadfence();
        float s = 0.f;
        for (int idx = t; idx < n; idx += 256) {
            float ap = sqrtf(__uint_as_float(g_ap[idx]));
            float an = sqrtf(__uint_as_float(g_an[idx]));
            s += fmaxf(ap - an + 0.3f, 0.f);
        }
        __shared__ float sh[8];
        for (int o = 16; o > 0; o >>= 1)
            s += __shfl_xor_sync(0xffffffffu, s, o);
        if ((t & 31) == 0) sh[t >> 5] = s;
        __syncthreads();
        if (t < 32) {
            float v = (t < 8) ? sh[t] : 0.f;
            for (int o = 4; o > 0; o >>= 1)
                v += __shfl_xor_sync(0xffffffffu, v, o);
            if (t == 0) {
                out[0] = v / (float)n;
                g_done = 0;   // reset for next graph replay
            }
        }
    }
}

extern "C" void kernel_launch(void* const* d_in, const int* in_sizes, int n_in,
                              void* d_out, int out_size) {
    const float* X = (const float*)d_in[0];
    const void*  Y = d_in[1];
    int n = in_sizes[1];                 // 4096
    int d = in_sizes[0] / n;             // 2048
    float* out = (float*)d_out;

    static int smem_set = 0;
    if (!smem_set) {
        cudaFuncSetAttribute(k_mma,
                             cudaFuncAttributeMaxDynamicSharedMemorySize,
                             SMEM_BYTES);
        smem_set = 1;
    }

    k_prep<<<n, 256>>>(X, Y, n, d);

    int nt = n / BM;
    int nblocks = nt * (nt + 1) / 2;     // 528
    k_mma<<<nblocks, 256, SMEM_BYTES>>>(n, d, out);
}